// round 8
// baseline (speedup 1.0000x reference)
#include <cuda_runtime.h>
#include <cuda_fp16.h>
#include <cstdint>

// ============================================================================
// Problem constants
// ============================================================================
#define NROWS 16384
#define DDIM  128
#define TILE  128
#define NJOBS 16384              // 128 row-blocks x 128 col-tiles

static __device__ __half g_Ah[NROWS * DDIM];  // normalized * C_EXP (f16)
static __device__ __half g_Ph[NROWS * DDIM];  // normalized (f16)
static __device__ float g_partS[NROWS];   // per-row expsum (atomic-accumulated)
static __device__ float g_acc;

// grid-barrier state (zero-initialized; restored at end of each launch)
static __device__ unsigned g_bcnt[3];
static __device__ unsigned g_bflag[3];
static __device__ unsigned g_done;

#define C_EXP   20.609929155556620f   // log2(e)/0.07, folded into A
#define LN2     0.69314718055994531f  // diag: dot/T = (C_EXP*dot)*ln2

// SMEM: 3 rotating 128x128 f16 slabs (272B padded rows). Slab @0 holds the
// A tile at segment start, then rejoins the B rotation (frags live in regs).
#define ROWB   272
#define SLAB   34816
#define SMEM_TOTAL (3 * 34816)

// ============================================================================
// PTX helpers (sm_80+ portable; ptxas target is plain sm_100 -> no tcgen05)
// ============================================================================
__device__ __forceinline__ uint32_t smem_to_u32(const void* p) {
    uint32_t a;
    asm("{ .reg .u64 t; cvta.to.shared.u64 t, %1; cvt.u32.u64 %0, t; }" : "=r"(a) : "l"(p));
    return a;
}
__device__ __forceinline__ uint32_t ex2_f16x2(uint32_t x) {
    uint32_t y; asm("ex2.approx.f16x2 %0, %1;" : "=r"(y) : "r"(x)); return y;
}
__device__ __forceinline__ uint32_t hadd2(uint32_t a, uint32_t b) {
    uint32_t r; asm("add.f16x2 %0, %1, %2;" : "=r"(r) : "r"(a), "r"(b)); return r;
}
__device__ __forceinline__ float h2sum(uint32_t h) {
    __half2 v = *reinterpret_cast<__half2*>(&h);
    float2 f = __half22float2(v);
    return f.x + f.y;
}

#define LDSM_X4(r0, r1, r2, r3, addr) \
    asm volatile("ldmatrix.sync.aligned.m8n8.x4.shared.b16 {%0,%1,%2,%3}, [%4];" \
        : "=r"(r0), "=r"(r1), "=r"(r2), "=r"(r3) : "r"(addr))

// full-f16 HMMA: D(f16x2 x2) = A(f16) * B(f16) + D
#define MMA_F16(d, a, b0, b1) \
    asm volatile("mma.sync.aligned.m16n8k16.row.col.f16.f16.f16.f16 " \
        "{%0,%1},{%2,%3,%4,%5},{%6,%7},{%0,%1};" \
        : "+r"((d)[0]), "+r"((d)[1]) \
        : "r"((a)[0]), "r"((a)[1]), "r"((a)[2]), "r"((a)[3]), "r"(b0), "r"(b1))

#define CP_ASYNC16(saddr, gptr) \
    asm volatile("cp.async.cg.shared.global [%0], [%1], 16;" :: "r"(saddr), "l"(gptr))
#define CP_COMMIT() asm volatile("cp.async.commit_group;")
#define CP_WAIT1()  asm volatile("cp.async.wait_group 1;")
#define CP_WAIT2()  asm volatile("cp.async.wait_group 2;")

// Grid-wide barrier: all gridDim.x CTAs co-resident (persistent launch).
__device__ __forceinline__ void grid_barrier(int idx, int G) {
    __syncthreads();
    if (threadIdx.x == 0) {
        __threadfence();
        unsigned t = atomicAdd(&g_bcnt[idx], 1u);
        if (t == (unsigned)(G - 1)) {
            atomicExch(&g_bflag[idx], 1u);
        } else {
            while (atomicAdd(&g_bflag[idx], 0u) == 0u) { }
        }
        __threadfence();
    }
    __syncthreads();
}

// ============================================================================
// cp.async loader: 128x128 f16 tile (row-major) -> padded SMEM (272B rows)
// ============================================================================
__device__ __forceinline__ void cp_tile(uint32_t sbase, const __half* gsrc, int tid) {
    const char* g = reinterpret_cast<const char*>(gsrc);
    #pragma unroll
    for (int i = 0; i < 8; i++) {
        int idx = tid + i * 256;          // 2048 chunks of 16B
        int row = idx >> 4;
        int c   = idx & 15;
        uint32_t s = sbase + row * ROWB + c * 16;
        CP_ASYNC16(s, g + idx * 16);
    }
}

// ============================================================================
// THE kernel: normalize -> barrier -> f16 GEMM + exp rowsum -> barrier ->
//             exact diag + rowsum -> barrier -> finalize -> reset barriers
// ============================================================================
__global__ void __launch_bounds__(256, 2) infonce_fused_kernel(
        const float* __restrict__ A, const float* __restrict__ P,
        float* __restrict__ out) {
    extern __shared__ char smem[];
    uint32_t sb = smem_to_u32(smem);
    int tid = threadIdx.x;
    int lane = tid & 31;
    int w = tid >> 5;
    int G = gridDim.x;

    // ---------------- Phase 0: zero partS/acc + normalize -> f16 -----------
    {
        int gid = blockIdx.x * 256 + tid;
        if (gid == 0) g_acc = 0.0f;
        for (int r = gid; r < NROWS; r += G * 256) g_partS[r] = 0.0f;

        int gw = blockIdx.x * 8 + w;
        for (int i = gw; i < 2 * NROWS; i += G * 8) {
            const float* src;
            __half* dst;
            float extra;
            if (i < NROWS) {
                src = A + (size_t)i * DDIM; dst = g_Ah + (size_t)i * DDIM; extra = C_EXP;
            } else {
                int r = i - NROWS;
                src = P + (size_t)r * DDIM; dst = g_Ph + (size_t)r * DDIM; extra = 1.0f;
            }
            float4 v = reinterpret_cast<const float4*>(src)[lane];
            float ss = v.x * v.x + v.y * v.y + v.z * v.z + v.w * v.w;
            #pragma unroll
            for (int o = 16; o > 0; o >>= 1) ss += __shfl_xor_sync(0xFFFFFFFFu, ss, o);
            float s = extra / fmaxf(sqrtf(ss), 1e-12f);
            __half2 h0 = __floats2half2_rn(v.x * s, v.y * s);
            __half2 h1 = __floats2half2_rn(v.z * s, v.w * s);
            reinterpret_cast<__half2*>(dst)[lane * 2 + 0] = h0;
            reinterpret_cast<__half2*>(dst)[lane * 2 + 1] = h1;
        }
    }
    grid_barrier(0, G);

    // ---------------- Phase 1: persistent balanced fused GEMM --------------
    {
        int wr = w >> 1;            // row-group 0..3 (32 rows)
        int wc = w & 1;             // col-group 0..1 (64 cols)
        int cstag = (w >> 2) << 1;  // chunk stagger: warps 0-3 vs 4-7
        int j0 = (int)(((long long)blockIdx.x * NJOBS) / G);
        int j1 = (int)(((long long)(blockIdx.x + 1) * NJOBS) / G);

        int g = lane >> 2;
        int tig = lane & 3;
        uint32_t b_lane_off = (uint32_t)(((lane & 7) + ((lane >> 4) << 3)) * ROWB
                                         + ((lane >> 3) & 1) * 16)
                              + (uint32_t)(wc * 64) * ROWB;
        const uint32_t bufoff[3] = {SLAB, 2 * SLAB, 0};

        int j = j0;
        while (j < j1) {
            int rb = j >> 7;
            int c0 = j & 127;
            int cend = min(j1 - (rb << 7), 128);
            int nt = cend - c0;

            __syncthreads();   // previous segment's smem is free

            cp_tile(sb + 0, g_Ah + (size_t)rb * TILE * DDIM, tid);
            CP_COMMIT();
            cp_tile(sb + bufoff[0], g_Ph + (size_t)c0 * TILE * DDIM, tid);
            CP_COMMIT();
            if (nt > 1)
                cp_tile(sb + bufoff[1], g_Ph + (size_t)(c0 + 1) * TILE * DDIM, tid);
            CP_COMMIT();
            CP_WAIT2();
            __syncthreads();

            uint32_t afrag[8][2][4];
            #pragma unroll
            for (int f = 0; f < 2; f++) {
                uint32_t a_addr = sb + (wr * 32 + f * 16 + (lane & 15)) * ROWB
                                  + (lane >> 4) * 16;
                #pragma unroll
                for (int k = 0; k < 8; k++)
                    LDSM_X4(afrag[k][f][0], afrag[k][f][1], afrag[k][f][2], afrag[k][f][3],
                            a_addr + k * 32);
            }

            float S[4] = {0.f, 0.f, 0.f, 0.f};
            int curbuf = 0, nxtbuf = 2;

            for (int t = 0; t < nt; t++) {
                CP_WAIT1();
                __syncthreads();
                if (t + 2 < nt)
                    cp_tile(sb + bufoff[nxtbuf],
                            g_Ph + (size_t)(c0 + t + 2) * TILE * DDIM, tid);
                CP_COMMIT();

                uint32_t bbase = sb + bufoff[curbuf] + b_lane_off;
                uint32_t hS[4] = {0u, 0u, 0u, 0u};   // per-tile f16x2 partials

                #pragma unroll
                for (int cc = 0; cc < 4; cc++) {
                    int c = cc ^ cstag;   // stagger chunk order across SMSP pairs
                    uint32_t acc[2][2][2];  // f16x2 accumulators
                    #pragma unroll
                    for (int f = 0; f < 2; f++)
                        #pragma unroll
                        for (int nb = 0; nb < 2; nb++) {
                            acc[f][nb][0] = 0u; acc[f][nb][1] = 0u;
                        }

                    uint32_t bchunk = bbase + (uint32_t)(c * 16) * ROWB;
                    #pragma unroll
                    for (int k = 0; k < 8; k++) {
                        uint32_t b0, b1, b2, b3;
                        LDSM_X4(b0, b1, b2, b3, bchunk + k * 32);
                        MMA_F16(acc[0][0], afrag[k][0], b0, b1);
                        MMA_F16(acc[0][1], afrag[k][0], b2, b3);
                        MMA_F16(acc[1][0], afrag[k][1], b0, b1);
                        MMA_F16(acc[1][1], afrag[k][1], b2, b3);
                    }
                    // epilogue: exp2 on f16x2 pairs, accumulate in f16x2
                    #pragma unroll
                    for (int f = 0; f < 2; f++)
                        #pragma unroll
                        for (int nb = 0; nb < 2; nb++) {
                            hS[f * 2 + 0] = hadd2(hS[f * 2 + 0], ex2_f16x2(acc[f][nb][0]));
                            hS[f * 2 + 1] = hadd2(hS[f * 2 + 1], ex2_f16x2(acc[f][nb][1]));
                        }
                }
                // flush per-tile f16 partials into f32 row sums
                S[0] += h2sum(hS[0]); S[1] += h2sum(hS[1]);
                S[2] += h2sum(hS[2]); S[3] += h2sum(hS[3]);

                if (++curbuf == 3) curbuf = 0;
                if (++nxtbuf == 3) nxtbuf = 0;
            }

            // segment flush: reduce across the 4 threads sharing each row
            #pragma unroll
            for (int i = 0; i < 4; i++) {
                S[i] += __shfl_xor_sync(0xFFFFFFFFu, S[i], 1);
                S[i] += __shfl_xor_sync(0xFFFFFFFFu, S[i], 2);
            }
            if (tig == 0) {
                #pragma unroll
                for (int i = 0; i < 4; i++) {
                    int row_local = wr * 32 + (i >> 1) * 16 + (i & 1) * 8 + g;
                    atomicAdd(&g_partS[rb * TILE + row_local], S[i]);
                }
            }
            j += nt;
        }
    }
    grid_barrier(1, G);

    // -------- Phase 2: exact diag (f32 dot of f16 rows) + per-row loss -----
    {
        int gw = blockIdx.x * 8 + w;
        for (int row = gw; row < NROWS; row += G * 8) {
            const __half2* ar = reinterpret_cast<const __half2*>(g_Ah + (size_t)row * DDIM);
            const __half2* pr = reinterpret_cast<const __half2*>(g_Ph + (size_t)row * DDIM);
            float dot = 0.0f;
            #pragma unroll
            for (int i = 0; i < 2; i++) {
                float2 a2 = __half22float2(ar[lane * 2 + i]);
                float2 p2 = __half22float2(pr[lane * 2 + i]);
                dot += a2.x * p2.x + a2.y * p2.y;
            }
            #pragma unroll
            for (int o = 16; o > 0; o >>= 1) dot += __shfl_xor_sync(0xFFFFFFFFu, dot, o);
            if (lane == 0) {
                // dot is in log2-units (C_EXP folded into A); *LN2 -> nat units
                float v = logf(g_partS[row]) - dot * LN2;
                atomicAdd(&g_acc, v);
            }
        }
    }
    grid_barrier(2, G);

    // ---------------- Phase 3: finalize ------------------------------------
    if (blockIdx.x == 0 && tid == 0) out[0] = g_acc * (1.0f / (float)NROWS);

    // ---------------- Reset barrier state for the next graph replay --------
    __syncthreads();
    if (tid == 0) {
        unsigned t = atomicAdd(&g_done, 1u);
        if (t == (unsigned)(G - 1)) {
            g_bcnt[0] = 0; g_bcnt[1] = 0; g_bcnt[2] = 0;
            g_bflag[0] = 0; g_bflag[1] = 0; g_bflag[2] = 0;
            g_done = 0;
            __threadfence();
        }
    }
}

// ============================================================================
// Launch
// ============================================================================
extern "C" void kernel_launch(void* const* d_in, const int* in_sizes, int n_in,
                              void* d_out, int out_size) {
    const float* A = (const float*)d_in[0];
    const float* P = (const float*)d_in[1];
    int nsm = 148;
    cudaDeviceGetAttribute(&nsm, cudaDevAttrMultiProcessorCount, 0);
    cudaFuncSetAttribute(infonce_fused_kernel,
                         cudaFuncAttributeMaxDynamicSharedMemorySize, SMEM_TOTAL);
    infonce_fused_kernel<<<2 * nsm, 256, SMEM_TOTAL>>>(A, P, (float*)d_out);
}

// round 9
// speedup vs baseline: 1.0060x; 1.0060x over previous
#include <cuda_runtime.h>
#include <cuda_fp16.h>
#include <cstdint>

// ============================================================================
// Problem constants
// ============================================================================
#define NROWS 16384
#define DDIM  128
#define TILE  128
#define NJOBS 16384              // 128 row-blocks x 128 col-tiles

static __device__ __half g_Ah[NROWS * DDIM];  // normalized * C_EXP (f16)
static __device__ __half g_Ph[NROWS * DDIM];  // normalized (f16)
static __device__ float g_partS[NROWS];   // per-row expsum (atomic-accumulated)
static __device__ float g_acc;

// grid-barrier state (zero-initialized; restored at end of each launch)
static __device__ unsigned g_bcnt[3];
static __device__ unsigned g_bflag[3];
static __device__ unsigned g_done;

#define C_EXP   20.609929155556620f   // log2(e)/0.07, folded into A
#define LN2     0.69314718055994531f  // diag: dot/T = (C_EXP*dot)*ln2

// SMEM: 3 rotating 128x128 f16 slabs (272B padded rows). Slab @0 holds the
// A tile at segment start, then rejoins the B rotation (frags live in regs).
#define ROWB   272
#define SLAB   34816
#define SMEM_TOTAL (3 * 34816)

// ============================================================================
// PTX helpers (sm_80+ portable; ptxas target is plain sm_100 -> no tcgen05)
// ============================================================================
__device__ __forceinline__ uint32_t smem_to_u32(const void* p) {
    uint32_t a;
    asm("{ .reg .u64 t; cvta.to.shared.u64 t, %1; cvt.u32.u64 %0, t; }" : "=r"(a) : "l"(p));
    return a;
}
__device__ __forceinline__ float ex2f_fast(float x) {
    float y; asm("ex2.approx.ftz.f32 %0, %1;" : "=f"(y) : "f"(x)); return y;
}

#define LDSM_X4(r0, r1, r2, r3, addr) \
    asm volatile("ldmatrix.sync.aligned.m8n8.x4.shared.b16 {%0,%1,%2,%3}, [%4];" \
        : "=r"(r0), "=r"(r1), "=r"(r2), "=r"(r3) : "r"(addr))

// f16 inputs, f32 accumulator (the fast legacy-HMMA config: rt~7.6)
#define MMA_F16F32(d, a, b0, b1) \
    asm volatile("mma.sync.aligned.m16n8k16.row.col.f32.f16.f16.f32 " \
        "{%0,%1,%2,%3},{%4,%5,%6,%7},{%8,%9},{%0,%1,%2,%3};" \
        : "+f"((d)[0]), "+f"((d)[1]), "+f"((d)[2]), "+f"((d)[3]) \
        : "r"((a)[0]), "r"((a)[1]), "r"((a)[2]), "r"((a)[3]), "r"(b0), "r"(b1))

#define CP_ASYNC16(saddr, gptr) \
    asm volatile("cp.async.cg.shared.global [%0], [%1], 16;" :: "r"(saddr), "l"(gptr))
#define CP_COMMIT() asm volatile("cp.async.commit_group;")
#define CP_WAIT1()  asm volatile("cp.async.wait_group 1;")
#define CP_WAIT2()  asm volatile("cp.async.wait_group 2;")

// Grid-wide barrier: all gridDim.x CTAs co-resident (persistent launch).
__device__ __forceinline__ void grid_barrier(int idx, int G) {
    __syncthreads();
    if (threadIdx.x == 0) {
        __threadfence();
        unsigned t = atomicAdd(&g_bcnt[idx], 1u);
        if (t == (unsigned)(G - 1)) {
            atomicExch(&g_bflag[idx], 1u);
        } else {
            while (atomicAdd(&g_bflag[idx], 0u) == 0u) { }
        }
        __threadfence();
    }
    __syncthreads();
}

// ============================================================================
// cp.async loader: 128x128 f16 tile (row-major) -> padded SMEM (272B rows)
// ============================================================================
__device__ __forceinline__ void cp_tile(uint32_t sbase, const __half* gsrc, int tid) {
    const char* g = reinterpret_cast<const char*>(gsrc);
    #pragma unroll
    for (int i = 0; i < 8; i++) {
        int idx = tid + i * 256;          // 2048 chunks of 16B
        int row = idx >> 4;
        int c   = idx & 15;
        uint32_t s = sbase + row * ROWB + c * 16;
        CP_ASYNC16(s, g + idx * 16);
    }
}

// ============================================================================
// THE kernel: normalize -> barrier -> GEMM+exp rowsum (uniform path) ->
//             barrier -> exact diag + rowsum -> barrier -> finalize -> reset
// ============================================================================
__global__ void __launch_bounds__(256, 2) infonce_fused_kernel(
        const float* __restrict__ A, const float* __restrict__ P,
        float* __restrict__ out) {
    extern __shared__ char smem[];
    uint32_t sb = smem_to_u32(smem);
    int tid = threadIdx.x;
    int lane = tid & 31;
    int w = tid >> 5;
    int G = gridDim.x;

    // ---------------- Phase 0: zero partS/acc + normalize -> f16 -----------
    {
        int gid = blockIdx.x * 256 + tid;
        if (gid == 0) g_acc = 0.0f;
        for (int r = gid; r < NROWS; r += G * 256) g_partS[r] = 0.0f;

        int gw = blockIdx.x * 8 + w;
        for (int i = gw; i < 2 * NROWS; i += G * 8) {
            const float* src;
            __half* dst;
            float extra;
            if (i < NROWS) {
                src = A + (size_t)i * DDIM; dst = g_Ah + (size_t)i * DDIM; extra = C_EXP;
            } else {
                int r = i - NROWS;
                src = P + (size_t)r * DDIM; dst = g_Ph + (size_t)r * DDIM; extra = 1.0f;
            }
            float4 v = reinterpret_cast<const float4*>(src)[lane];
            float ss = v.x * v.x + v.y * v.y + v.z * v.z + v.w * v.w;
            #pragma unroll
            for (int o = 16; o > 0; o >>= 1) ss += __shfl_xor_sync(0xFFFFFFFFu, ss, o);
            float s = extra / fmaxf(sqrtf(ss), 1e-12f);
            __half2 h0 = __floats2half2_rn(v.x * s, v.y * s);
            __half2 h1 = __floats2half2_rn(v.z * s, v.w * s);
            reinterpret_cast<__half2*>(dst)[lane * 2 + 0] = h0;
            reinterpret_cast<__half2*>(dst)[lane * 2 + 1] = h1;
        }
    }
    grid_barrier(0, G);

    // ---------------- Phase 1: persistent balanced fused GEMM --------------
    {
        int wr = w >> 1;            // row-group 0..3 (32 rows)
        int wc = w & 1;             // col-group 0..1 (64 cols)
        int cstag = (w >> 2) << 1;  // chunk stagger: warps 0-3 order 0123, 4-7 order 2301
        int j0 = (int)(((long long)blockIdx.x * NJOBS) / G);
        int j1 = (int)(((long long)(blockIdx.x + 1) * NJOBS) / G);

        int g = lane >> 2;
        int tig = lane & 3;
        uint32_t b_lane_off = (uint32_t)(((lane & 7) + ((lane >> 4) << 3)) * ROWB
                                         + ((lane >> 3) & 1) * 16)
                              + (uint32_t)(wc * 64) * ROWB;
        const uint32_t bufoff[3] = {SLAB, 2 * SLAB, 0};

        int j = j0;
        while (j < j1) {
            int rb = j >> 7;
            int c0 = j & 127;
            int cend = min(j1 - (rb << 7), 128);
            int nt = cend - c0;

            __syncthreads();   // previous segment's smem is free

            cp_tile(sb + 0, g_Ah + (size_t)rb * TILE * DDIM, tid);
            CP_COMMIT();
            cp_tile(sb + bufoff[0], g_Ph + (size_t)c0 * TILE * DDIM, tid);
            CP_COMMIT();
            if (nt > 1)
                cp_tile(sb + bufoff[1], g_Ph + (size_t)(c0 + 1) * TILE * DDIM, tid);
            CP_COMMIT();
            CP_WAIT2();
            __syncthreads();

            uint32_t afrag[8][2][4];
            #pragma unroll
            for (int f = 0; f < 2; f++) {
                uint32_t a_addr = sb + (wr * 32 + f * 16 + (lane & 15)) * ROWB
                                  + (lane >> 4) * 16;
                #pragma unroll
                for (int k = 0; k < 8; k++)
                    LDSM_X4(afrag[k][f][0], afrag[k][f][1], afrag[k][f][2], afrag[k][f][3],
                            a_addr + k * 32);
            }

            float S[4] = {0.f, 0.f, 0.f, 0.f};
            int curbuf = 0, nxtbuf = 2;

            for (int t = 0; t < nt; t++) {
                CP_WAIT1();
                __syncthreads();
                if (t + 2 < nt)
                    cp_tile(sb + bufoff[nxtbuf],
                            g_Ph + (size_t)(c0 + t + 2) * TILE * DDIM, tid);
                CP_COMMIT();

                uint32_t bbase = sb + bufoff[curbuf] + b_lane_off;

                // ---- uniform fast path: no diag checks ----
                #pragma unroll
                for (int cc = 0; cc < 4; cc++) {
                    int c = cc ^ cstag;   // stagger chunk order across warp halves
                    float acc[2][2][4];
                    #pragma unroll
                    for (int f = 0; f < 2; f++)
                        #pragma unroll
                        for (int nb = 0; nb < 2; nb++)
                            #pragma unroll
                            for (int q = 0; q < 4; q++) acc[f][nb][q] = 0.0f;

                    uint32_t bchunk = bbase + (uint32_t)(c * 16) * ROWB;
                    #pragma unroll
                    for (int k = 0; k < 8; k++) {
                        uint32_t b0, b1, b2, b3;
                        LDSM_X4(b0, b1, b2, b3, bchunk + k * 32);
                        MMA_F16F32(acc[0][0], afrag[k][0], b0, b1);
                        MMA_F16F32(acc[0][1], afrag[k][0], b2, b3);
                        MMA_F16F32(acc[1][0], afrag[k][1], b0, b1);
                        MMA_F16F32(acc[1][1], afrag[k][1], b2, b3);
                    }
                    #pragma unroll
                    for (int f = 0; f < 2; f++)
                        #pragma unroll
                        for (int nb = 0; nb < 2; nb++)
                            #pragma unroll
                            for (int q = 0; q < 4; q++)
                                S[f * 2 + (q >> 1)] += ex2f_fast(acc[f][nb][q]);
                }
                if (++curbuf == 3) curbuf = 0;
                if (++nxtbuf == 3) nxtbuf = 0;
            }

            // segment flush: reduce across the 4 threads sharing each row
            #pragma unroll
            for (int i = 0; i < 4; i++) {
                S[i] += __shfl_xor_sync(0xFFFFFFFFu, S[i], 1);
                S[i] += __shfl_xor_sync(0xFFFFFFFFu, S[i], 2);
            }
            if (tig == 0) {
                #pragma unroll
                for (int i = 0; i < 4; i++) {
                    int row_local = wr * 32 + (i >> 1) * 16 + (i & 1) * 8 + g;
                    atomicAdd(&g_partS[rb * TILE + row_local], S[i]);
                }
            }
            j += nt;
        }
    }
    grid_barrier(1, G);

    // -------- Phase 2: exact diag (f32 dot of f16 rows) + per-row loss -----
    {
        int gw = blockIdx.x * 8 + w;
        for (int row = gw; row < NROWS; row += G * 8) {
            const __half2* ar = reinterpret_cast<const __half2*>(g_Ah + (size_t)row * DDIM);
            const __half2* pr = reinterpret_cast<const __half2*>(g_Ph + (size_t)row * DDIM);
            float dot = 0.0f;
            #pragma unroll
            for (int i = 0; i < 2; i++) {
                float2 a2 = __half22float2(ar[lane * 2 + i]);
                float2 p2 = __half22float2(pr[lane * 2 + i]);
                dot += a2.x * p2.x + a2.y * p2.y;
            }
            #pragma unroll
            for (int o = 16; o > 0; o >>= 1) dot += __shfl_xor_sync(0xFFFFFFFFu, dot, o);
            if (lane == 0) {
                // dot is in log2-units (C_EXP folded into A); *LN2 -> nat units
                float v = logf(g_partS[row]) - dot * LN2;
                atomicAdd(&g_acc, v);
            }
        }
    }
    grid_barrier(2, G);

    // ---------------- Phase 3: finalize ------------------------------------
    if (blockIdx.x == 0 && tid == 0) out[0] = g_acc * (1.0f / (float)NROWS);

    // ---------------- Reset barrier state for the next graph replay --------
    __syncthreads();
    if (tid == 0) {
        unsigned t = atomicAdd(&g_done, 1u);
        if (t == (unsigned)(G - 1)) {
            g_bcnt[0] = 0; g_bcnt[1] = 0; g_bcnt[2] = 0;
            g_bflag[0] = 0; g_bflag[1] = 0; g_bflag[2] = 0;
            g_done = 0;
            __threadfence();
        }
    }
}

// ============================================================================
// Launch
// ============================================================================
extern "C" void kernel_launch(void* const* d_in, const int* in_sizes, int n_in,
                              void* d_out, int out_size) {
    const float* A = (const float*)d_in[0];
    const float* P = (const float*)d_in[1];
    int nsm = 148;
    cudaDeviceGetAttribute(&nsm, cudaDevAttrMultiProcessorCount, 0);
    cudaFuncSetAttribute(infonce_fused_kernel,
                         cudaFuncAttributeMaxDynamicSharedMemorySize, SMEM_TOTAL);
    infonce_fused_kernel<<<2 * nsm, 256, SMEM_TOTAL>>>(A, P, (float*)d_out);
}

// round 10
// speedup vs baseline: 1.1996x; 1.1924x over previous
#include <cuda_runtime.h>
#include <cuda_bf16.h>
#include <cstdint>

// ============================================================================
// Problem constants
// ============================================================================
#define NROWS 16384
#define DDIM  128
#define TILE  128
#define NJOBS 16384              // 128 row-blocks x 128 col-tiles

static __device__ __nv_bfloat16 g_Abf[NROWS * DDIM];  // normalized * C_EXP
static __device__ __nv_bfloat16 g_Pbf[NROWS * DDIM];  // normalized
static __device__ float g_partS[NROWS];   // per-row expsum (atomic-accumulated)
static __device__ float g_diagv[NROWS];   // C_EXP * diag dot (log2 units)
static __device__ float g_acc;

#define C_EXP   20.609929155556620f   // log2(e)/0.07, folded into A
#define LN2     0.69314718055994531f  // diag: dot/T = (C_EXP*dot)*ln2

// SMEM: 3 rotating 128x128 bf16 slabs (272B padded rows) + mbarrier block.
// Slab @0 (= bufoff index 2) holds the A tile at segment start, then rejoins
// the B rotation (A frags live in regs). Tile t lives in buffer (t % 3).
#define ROWB   272
#define SLAB   34816
#define BAR_OFF (3 * 34816)
#define SMEM_TOTAL (3 * 34816 + 128)

// ============================================================================
// PTX helpers (no arch-suffixed features; ptxas target is plain sm_100)
// ============================================================================
__device__ __forceinline__ uint32_t smem_to_u32(const void* p) {
    uint32_t a;
    asm("{ .reg .u64 t; cvta.to.shared.u64 t, %1; cvt.u32.u64 %0, t; }" : "=r"(a) : "l"(p));
    return a;
}
__device__ __forceinline__ float ex2f_fast(float x) {
    float y; asm("ex2.approx.ftz.f32 %0, %1;" : "=f"(y) : "f"(x)); return y;
}

#define LDSM_X4(r0, r1, r2, r3, addr) \
    asm volatile("ldmatrix.sync.aligned.m8n8.x4.shared.b16 {%0,%1,%2,%3}, [%4];" \
        : "=r"(r0), "=r"(r1), "=r"(r2), "=r"(r3) : "r"(addr))

#define MMA_BF16(d, a, b0, b1) \
    asm volatile("mma.sync.aligned.m16n8k16.row.col.f32.bf16.bf16.f32 " \
        "{%0,%1,%2,%3},{%4,%5,%6,%7},{%8,%9},{%0,%1,%2,%3};" \
        : "+f"((d)[0]), "+f"((d)[1]), "+f"((d)[2]), "+f"((d)[3]) \
        : "r"((a)[0]), "r"((a)[1]), "r"((a)[2]), "r"((a)[3]), "r"(b0), "r"(b1))

#define CP_ASYNC16(saddr, gptr) \
    asm volatile("cp.async.cg.shared.global [%0], [%1], 16;" :: "r"(saddr), "l"(gptr))
#define CP_COMMIT() asm volatile("cp.async.commit_group;")
#define CP_WAIT1()  asm volatile("cp.async.wait_group 1;")
#define CP_WAIT2()  asm volatile("cp.async.wait_group 2;")

#define MBAR_INVAL(a) \
    asm volatile("mbarrier.inval.shared.b64 [%0];" :: "r"(a) : "memory")
#define MBAR_INIT(a, cnt) \
    asm volatile("mbarrier.init.shared.b64 [%0], %1;" :: "r"(a), "r"(cnt) : "memory")
#define MBAR_ARRIVE(a) \
    asm volatile("{.reg .b64 s; mbarrier.arrive.shared.b64 s, [%0];}" :: "r"(a) : "memory")
#define MBAR_WAIT(a, par) do { \
    uint32_t _done; \
    asm volatile("{\n\t.reg .pred p;\n\t" \
        "mbarrier.try_wait.parity.acquire.cta.shared::cta.b64 p, [%1], %2;\n\t" \
        "selp.b32 %0, 1, 0, p;\n\t}" : "=r"(_done) : "r"(a), "r"(par) : "memory"); \
    while (!_done) { \
        asm volatile("{\n\t.reg .pred p;\n\t" \
            "mbarrier.try_wait.parity.acquire.cta.shared::cta.b64 p, [%1], %2;\n\t" \
            "selp.b32 %0, 1, 0, p;\n\t}" : "=r"(_done) : "r"(a), "r"(par) : "memory"); \
    } \
} while (0)

// ============================================================================
// Kernel 1: normalize rows (fp32) -> bf16 (A scaled by C_EXP); zero partS+acc
// ============================================================================
__global__ void __launch_bounds__(256) normalize_kernel(const float* __restrict__ A,
                                                        const float* __restrict__ P) {
    int gid = blockIdx.x * blockDim.x + threadIdx.x;
    if (gid == 0) g_acc = 0.0f;
    if (gid < NROWS) g_partS[gid] = 0.0f;
    int warp = gid >> 5;
    int lane = threadIdx.x & 31;
    if (warp >= 2 * NROWS) return;
    const float* src;
    __nv_bfloat16* dst;
    float extra;
    if (warp < NROWS) {
        src = A + (size_t)warp * DDIM; dst = g_Abf + (size_t)warp * DDIM; extra = C_EXP;
    } else {
        int r = warp - NROWS;
        src = P + (size_t)r * DDIM; dst = g_Pbf + (size_t)r * DDIM; extra = 1.0f;
    }
    float4 v = reinterpret_cast<const float4*>(src)[lane];
    float ss = v.x * v.x + v.y * v.y + v.z * v.z + v.w * v.w;
    #pragma unroll
    for (int o = 16; o > 0; o >>= 1) ss += __shfl_xor_sync(0xFFFFFFFFu, ss, o);
    float s = extra / fmaxf(sqrtf(ss), 1e-12f);
    __nv_bfloat162 h0 = __floats2bfloat162_rn(v.x * s, v.y * s);
    __nv_bfloat162 h1 = __floats2bfloat162_rn(v.z * s, v.w * s);
    reinterpret_cast<__nv_bfloat162*>(dst)[lane * 2 + 0] = h0;
    reinterpret_cast<__nv_bfloat162*>(dst)[lane * 2 + 1] = h1;
}

// ============================================================================
// cp.async loader: 128x128 bf16 tile (row-major) -> padded SMEM (272B rows)
// ============================================================================
__device__ __forceinline__ void cp_tile(uint32_t sbase, const __nv_bfloat16* gsrc, int tid) {
    const char* g = reinterpret_cast<const char*>(gsrc);
    #pragma unroll
    for (int i = 0; i < 8; i++) {
        int idx = tid + i * 256;          // 2048 chunks of 16B
        int row = idx >> 4;
        int c   = idx & 15;
        uint32_t s = sbase + row * ROWB + c * 16;
        CP_ASYNC16(s, g + idx * 16);
    }
}

// ============================================================================
// Kernel 2: persistent balanced fused GEMM + exp rowsum + diag.
// mbarrier full/empty pipeline: empty-arrivals fire after LDSM (pre-epilogue),
// chunk-3 epilogue deferred into the arrive->wait(full) gap, no __syncthreads
// in the tile loop. Tile t uses buffer t%3; both wait parities = (t/3)&1.
// ============================================================================
__global__ void __launch_bounds__(256, 2) infonce_main_kernel() {
    extern __shared__ char smem[];
    uint32_t sb = smem_to_u32(smem);
    int tid = threadIdx.x;
    int lane = tid & 31;
    int w = tid >> 5;
    int wr = w >> 1;            // row-group 0..3 (32 rows)
    int wc = w & 1;             // col-group 0..1 (64 cols)

    int G = gridDim.x;
    int j0 = (int)(((long long)blockIdx.x * NJOBS) / G);
    int j1 = (int)(((long long)(blockIdx.x + 1) * NJOBS) / G);

    int g = lane >> 2;
    int tig = lane & 3;
    uint32_t b_lane_off = (uint32_t)(((lane & 7) + ((lane >> 4) << 3)) * ROWB
                                     + ((lane >> 3) & 1) * 16)
                          + (uint32_t)(wc * 64) * ROWB;
    // tile t -> buffer t%3; buffer i at bufoff[i]. Buffer 2 = A slab (@0).
    const uint32_t bufoff[3] = {SLAB, 2 * SLAB, 0};
    uint32_t bfull[3], bempty[3];
    #pragma unroll
    for (int i = 0; i < 3; i++) {
        bfull[i]  = sb + BAR_OFF + i * 8;
        bempty[i] = sb + BAR_OFF + 24 + i * 8;
    }

    int j = j0;
    while (j < j1) {
        int rb = j >> 7;
        int c0 = j & 127;
        int cend = min(j1 - (rb << 7), 128);
        int nt = cend - c0;

        __syncthreads();   // previous segment fully done with smem
        if (tid == 0) {
            #pragma unroll
            for (int i = 0; i < 3; i++) {
                MBAR_INVAL(bfull[i]);  MBAR_INIT(bfull[i], 256u);
                MBAR_INVAL(bempty[i]); MBAR_INIT(bempty[i], 256u);
            }
        }
        __syncthreads();   // barriers initialized

        // Prologue: A -> slab0 (buffer 2); tile c0 -> buf0; tile c0+1 -> buf1
        cp_tile(sb + bufoff[2], g_Abf + (size_t)rb * TILE * DDIM, tid);
        CP_COMMIT();
        cp_tile(sb + bufoff[0], g_Pbf + (size_t)c0 * TILE * DDIM, tid);
        CP_COMMIT();
        if (nt > 1)
            cp_tile(sb + bufoff[1], g_Pbf + (size_t)(c0 + 1) * TILE * DDIM, tid);
        CP_COMMIT();
        CP_WAIT2();        // A done locally (b0,b1 may pend)
        __syncthreads();   // A visible to all threads

        // A fragments: 8 k-steps x 2 m16-frags x 4 regs
        uint32_t afrag[8][2][4];
        #pragma unroll
        for (int f = 0; f < 2; f++) {
            uint32_t a_addr = sb + bufoff[2] + (wr * 32 + f * 16 + (lane & 15)) * ROWB
                              + (lane >> 4) * 16;
            #pragma unroll
            for (int k = 0; k < 8; k++)
                LDSM_X4(afrag[k][f][0], afrag[k][f][1], afrag[k][f][2], afrag[k][f][3],
                        a_addr + k * 32);
        }
        MBAR_ARRIVE(bempty[2]);   // frag-load = buffer 2's gen-0 consumption
        CP_WAIT1();               // tile c0's group done locally (b1 may pend)
        MBAR_ARRIVE(bfull[0]);    // announce tile 0 ready (this thread)

        float S[4] = {0.f, 0.f, 0.f, 0.f};
        float d[4] = {0.f, 0.f, 0.f, 0.f};

        for (int t = 0; t < nt; t++) {
            int buf = t % 3;                 // modulus of small t: cheap
            uint32_t par = (uint32_t)((t / 3) & 1);
            MBAR_WAIT(bfull[buf], par);      // tile t data visible

            uint32_t bbase = sb + bufoff[buf] + b_lane_off;
            int diag_t = (c0 + t == rb);
            float pend[16];

            // chunks 0..2: MMA + inline epilogue
            #pragma unroll
            for (int c = 0; c < 3; c++) {
                float acc[16];
                #pragma unroll
                for (int q = 0; q < 16; q++) acc[q] = 0.0f;
                uint32_t bchunk = bbase + (uint32_t)(c * 16) * ROWB;
                #pragma unroll
                for (int k = 0; k < 8; k++) {
                    uint32_t b0, b1, b2, b3;
                    LDSM_X4(b0, b1, b2, b3, bchunk + k * 32);
                    MMA_BF16(acc + 0,  afrag[k][0], b0, b1);
                    MMA_BF16(acc + 4,  afrag[k][0], b2, b3);
                    MMA_BF16(acc + 8,  afrag[k][1], b0, b1);
                    MMA_BF16(acc + 12, afrag[k][1], b2, b3);
                }
                #pragma unroll
                for (int f = 0; f < 2; f++)
                    #pragma unroll
                    for (int nb = 0; nb < 2; nb++)
                        #pragma unroll
                        for (int q = 0; q < 4; q++) {
                            float v = acc[f * 8 + nb * 4 + q];
                            int hi = q >> 1;
                            S[f * 2 + hi] += ex2f_fast(v);
                            if (diag_t) {
                                int col_local = wc * 64 + c * 16 + nb * 8 + tig * 2 + (q & 1);
                                int row_local = wr * 32 + f * 16 + hi * 8 + g;
                                if (col_local == row_local) d[f * 2 + hi] = v;
                            }
                        }
            }
            // chunk 3: MMA only; epilogue deferred past the barrier ops
            {
                #pragma unroll
                for (int q = 0; q < 16; q++) pend[q] = 0.0f;
                uint32_t bchunk = bbase + (uint32_t)(3 * 16) * ROWB;
                #pragma unroll
                for (int k = 0; k < 8; k++) {
                    uint32_t b0, b1, b2, b3;
                    LDSM_X4(b0, b1, b2, b3, bchunk + k * 32);
                    MMA_BF16(pend + 0,  afrag[k][0], b0, b1);
                    MMA_BF16(pend + 4,  afrag[k][0], b2, b3);
                    MMA_BF16(pend + 8,  afrag[k][1], b0, b1);
                    MMA_BF16(pend + 12, afrag[k][1], b2, b3);
                }
            }
            MBAR_ARRIVE(bempty[buf]);        // all my LDSMs of tile t done

            // producer: write tile t+2 into buffer (t+2)%3 (holds tile t-1)
            if (t + 2 < nt) {
                int wbuf = (t + 2) % 3;
                MBAR_WAIT(bempty[wbuf], par);   // same (t/3)&1 parity
                cp_tile(sb + bufoff[wbuf], g_Pbf + (size_t)(c0 + t + 2) * TILE * DDIM, tid);
            }
            CP_COMMIT();
            CP_WAIT1();                       // tile t+1's group done locally
            if (t + 1 < nt) MBAR_ARRIVE(bfull[(t + 1) % 3]);

            // deferred chunk-3 epilogue fills the gap before next wait(full)
            #pragma unroll
            for (int f = 0; f < 2; f++)
                #pragma unroll
                for (int nb = 0; nb < 2; nb++)
                    #pragma unroll
                    for (int q = 0; q < 4; q++) {
                        float v = pend[f * 8 + nb * 4 + q];
                        int hi = q >> 1;
                        S[f * 2 + hi] += ex2f_fast(v);
                        if (diag_t) {
                            int col_local = wc * 64 + 3 * 16 + nb * 8 + tig * 2 + (q & 1);
                            int row_local = wr * 32 + f * 16 + hi * 8 + g;
                            if (col_local == row_local) d[f * 2 + hi] = v;
                        }
                    }
        }

        // segment flush: reduce across the 4 threads sharing each row
        #pragma unroll
        for (int i = 0; i < 4; i++) {
            S[i] += __shfl_xor_sync(0xFFFFFFFFu, S[i], 1);
            S[i] += __shfl_xor_sync(0xFFFFFFFFu, S[i], 2);
            d[i] += __shfl_xor_sync(0xFFFFFFFFu, d[i], 1);
            d[i] += __shfl_xor_sync(0xFFFFFFFFu, d[i], 2);
        }
        if (tig == 0) {
            int seg_has_diag = (rb >= c0) && (rb < cend);
            int wrote_diag = seg_has_diag && ((wr >> 1) == wc);
            #pragma unroll
            for (int i = 0; i < 4; i++) {
                int row_local = wr * 32 + (i >> 1) * 16 + (i & 1) * 8 + g;
                int row = rb * TILE + row_local;
                atomicAdd(&g_partS[row], S[i]);
                if (wrote_diag) g_diagv[row] = d[i];
            }
        }
        j += nt;
    }
}

// ============================================================================
// Kernel 3: per-row loss + global reduction (diag in log2 units -> *LN2)
// ============================================================================
__global__ void __launch_bounds__(256) rowsum_kernel() {
    int row = blockIdx.x * 256 + threadIdx.x;
    float v = logf(g_partS[row]) - g_diagv[row] * LN2;
    #pragma unroll
    for (int o = 16; o > 0; o >>= 1) v += __shfl_xor_sync(0xFFFFFFFFu, v, o);
    __shared__ float red[8];
    int lane = threadIdx.x & 31, wid = threadIdx.x >> 5;
    if (lane == 0) red[wid] = v;
    __syncthreads();
    if (wid == 0) {
        float s = (lane < 8) ? red[lane] : 0.0f;
        #pragma unroll
        for (int o = 4; o > 0; o >>= 1) s += __shfl_xor_sync(0xFFFFFFFFu, s, o);
        if (lane == 0) atomicAdd(&g_acc, s);
    }
}

// ============================================================================
// Kernel 4: finalize
// ============================================================================
__global__ void finalize_kernel(float* out) {
    out[0] = g_acc * (1.0f / (float)NROWS);
}

// ============================================================================
// Launch
// ============================================================================
extern "C" void kernel_launch(void* const* d_in, const int* in_sizes, int n_in,
                              void* d_out, int out_size) {
    const float* A = (const float*)d_in[0];
    const float* P = (const float*)d_in[1];
    int nsm = 148;
    cudaDeviceGetAttribute(&nsm, cudaDevAttrMultiProcessorCount, 0);
    cudaFuncSetAttribute(infonce_main_kernel,
                         cudaFuncAttributeMaxDynamicSharedMemorySize, SMEM_TOTAL);
    normalize_kernel<<<(2 * NROWS) / 8, 256>>>(A, P);
    infonce_main_kernel<<<2 * nsm, 256, SMEM_TOTAL>>>();
    rowsum_kernel<<<NROWS / 256, 256>>>();
    finalize_kernel<<<1, 1>>>((float*)d_out);
}